// round 9
// baseline (speedup 1.0000x reference)
#include <cuda_runtime.h>
#include <cuda_bf16.h>
#include <stdint.h>

#define BATCH 32
#define NPTS  8192
#define NCLST 64
#define C1    128
#define C2    256
#define CF    512
#define CO    384
#define PTOT  (BATCH*NPTS)
#define NFG   (BATCH*NCLST)
#define ENC_NEG_INF 0x007FFFFFu

#define ROWB   80
#define PLANE  (128*ROWB)        // bf16 core plane (10240)
#define BUFB   (4*PLANE)         // 40960
#define KC     32
#define SVSTR1 130               // stage1 epilogue tile stride (f32)
#define SVB1   (128*SVSTR1*4)    // 66560

// int8 core geometry: CTA 128 pts x 64 ch, k-chunk 64 int8 = 64B rows
#define PLANE_A (128*ROWB)       // 10240
#define PLANE_B (64*ROWB)        // 5120
#define BUF_I8  (2*PLANE_A + 2*PLANE_B)   // 30720
#define SVSTR3  67               // gemm3 epilogue tile stride

// ---------------- scratch ----------------
__device__ unsigned g_fg[NFG*C2];
__device__ unsigned g_om[NFG*CO];
__device__ int g_perm[PTOT];
__device__ int g_chs[PTOT];
__device__ __align__(16) uint16_t g_feat_h[(size_t)PTOT*C2];
__device__ __align__(16) uint16_t g_feat_l[(size_t)PTOT*C2];
__device__ __align__(16) uint16_t g_fg_h[NFG*C2];
__device__ __align__(16) uint16_t g_fg_l[NFG*C2];
__device__ __align__(16) uint16_t g_h2_h[(size_t)PTOT*CF];
__device__ __align__(16) uint16_t g_h2_l[(size_t)PTOT*CF];
__device__ __align__(16) uint16_t g_w2_h[C2*C1], g_w2_l[C2*C1];
__device__ __align__(16) uint16_t g_w3_h[CF*CF], g_w3_l[CF*CF];
// int8 quantized operands
__device__ __align__(16) int8_t g_q1f[(size_t)PTOT*C2], g_q2f[(size_t)PTOT*C2];
__device__ __align__(16) int8_t g_q1h[(size_t)PTOT*CF], g_q2h[(size_t)PTOT*CF];
__device__ __align__(16) int8_t g_w3q1[CF*C2], g_w3q2[CF*C2];    // rows=out ch, k in [256,512)
__device__ __align__(16) int8_t g_w4q1[CO*CF], g_w4q2[CO*CF];
__device__ float g_sAf[PTOT], g_sAh[PTOT], g_sB3[CF], g_sB4[CO];
__device__ float g_G[(size_t)NFG*CF];
__device__ float g_s2[CF], g_t2[CF];
__device__ __align__(16) float g_w1f[C1*4];

// ---------------- helpers ----------------
__device__ __forceinline__ unsigned enc(float f){
  unsigned u = __float_as_uint(f);
  return (u & 0x80000000u) ? ~u : (u | 0x80000000u);
}
__device__ __forceinline__ float dec(unsigned u){
  u = (u & 0x80000000u) ? (u & 0x7FFFFFFFu) : ~u;
  return __uint_as_float(u);
}
__device__ __forceinline__ void split2(float v, uint16_t& h, uint16_t& l){
  __nv_bfloat16 bh = __float2bfloat16(v);
  float r = v - __bfloat162float(bh);
  if (!(r == r)) r = 0.f;
  h = __bfloat16_as_ushort(bh);
  l = __bfloat16_as_ushort(__float2bfloat16(r));
}
__device__ __forceinline__ uint32_t smem_u32(const void* p){
  uint32_t a;
  asm("{ .reg .u64 t; cvta.to.shared.u64 t, %1; cvt.u32.u64 %0, t; }" : "=r"(a) : "l"(p));
  return a;
}
__device__ __forceinline__ void cp16(uint32_t dst, const void* src){
  asm volatile("cp.async.cg.shared.global [%0], [%1], 16;" :: "r"(dst), "l"(src));
}
#define CP_COMMIT() asm volatile("cp.async.commit_group;" ::: "memory")
#define CP_WAIT1()  asm volatile("cp.async.wait_group 1;"  ::: "memory")
#define CP_WAIT0()  asm volatile("cp.async.wait_group 0;"  ::: "memory")

__device__ __forceinline__ void ldsm4(uint32_t* r, uint32_t addr){
  asm volatile("ldmatrix.sync.aligned.m8n8.x4.shared.b16 {%0,%1,%2,%3}, [%4];"
    : "=r"(r[0]),"=r"(r[1]),"=r"(r[2]),"=r"(r[3]) : "r"(addr));
}
__device__ __forceinline__ void mma16816(float* c, const uint32_t* a, const uint32_t* b){
  asm volatile("mma.sync.aligned.m16n8k16.row.col.f32.bf16.bf16.f32 "
    "{%0,%1,%2,%3}, {%4,%5,%6,%7}, {%8,%9}, {%0,%1,%2,%3};"
    : "+f"(c[0]),"+f"(c[1]),"+f"(c[2]),"+f"(c[3])
    : "r"(a[0]),"r"(a[1]),"r"(a[2]),"r"(a[3]), "r"(b[0]),"r"(b[1]));
}
__device__ __forceinline__ void mma_s8(int* c, const uint32_t* a, const uint32_t* b){
  asm volatile("mma.sync.aligned.m16n8k32.row.col.s32.s8.s8.s32 "
    "{%0,%1,%2,%3}, {%4,%5,%6,%7}, {%8,%9}, {%0,%1,%2,%3};"
    : "+r"(c[0]),"+r"(c[1]),"+r"(c[2]),"+r"(c[3])
    : "r"(a[0]),"r"(a[1]),"r"(a[2]),"r"(a[3]), "r"(b[0]),"r"(b[1]));
}

__device__ __forceinline__ void q2e(float f, float inv, int& q1, int& q2){
  float x = f*inv;
  q1 = __float2int_rn(x);
  int t2i = __float2int_rn((x - (float)q1)*256.f);
  q2 = t2i > 127 ? 127 : (t2i < -128 ? -128 : t2i);
}
__device__ __forceinline__ uint32_t pk4(int a,int b,int c,int d){
  return (uint32_t)(uint8_t)a | ((uint32_t)(uint8_t)b<<8) |
         ((uint32_t)(uint8_t)c<<16) | ((uint32_t)(uint8_t)d<<24);
}
__device__ __forceinline__ void bpair(uint32_t h, uint32_t l, float& x, float& y){
  float2 fh = __bfloat1622float2(*reinterpret_cast<__nv_bfloat162*>(&h));
  float2 fl = __bfloat1622float2(*reinterpret_cast<__nv_bfloat162*>(&l));
  x = fh.x + fl.x; y = fh.y + fl.y;
}

// ============ bf16 split-3 core (stage1 / gemmC, proven) ============
struct Frag { float acc[4][4][4]; };

__device__ __forceinline__ void mma_chunk(uint32_t sb, uint32_t aoff, uint32_t boff, Frag& F){
  const uint32_t aAh = sb, aAl = sb + PLANE, aBh = sb + 2*PLANE, aBl = sb + 3*PLANE;
  #pragma unroll
  for (int ks = 0; ks < 2; ks++){
    const uint32_t kb = ks * 32;
    uint32_t a[4][4], bH[2][4], bL[2][4];
    #pragma unroll
    for (int mi=0;mi<4;mi++) ldsm4(a[mi],  aAh + aoff + mi*(16*ROWB) + kb);
    #pragma unroll
    for (int nj=0;nj<2;nj++) ldsm4(bH[nj], aBh + boff + nj*(16*ROWB) + kb);
    #pragma unroll
    for (int mi=0;mi<4;mi++)
      #pragma unroll
      for (int nj=0;nj<2;nj++){
        mma16816(F.acc[mi][nj*2+0], a[mi], &bH[nj][0]);
        mma16816(F.acc[mi][nj*2+1], a[mi], &bH[nj][2]);
      }
    #pragma unroll
    for (int nj=0;nj<2;nj++) ldsm4(bL[nj], aBl + boff + nj*(16*ROWB) + kb);
    #pragma unroll
    for (int mi=0;mi<4;mi++)
      #pragma unroll
      for (int nj=0;nj<2;nj++){
        mma16816(F.acc[mi][nj*2+0], a[mi], &bL[nj][0]);
        mma16816(F.acc[mi][nj*2+1], a[mi], &bL[nj][2]);
      }
    #pragma unroll
    for (int mi=0;mi<4;mi++) ldsm4(a[mi], aAl + aoff + mi*(16*ROWB) + kb);
    #pragma unroll
    for (int mi=0;mi<4;mi++)
      #pragma unroll
      for (int nj=0;nj<2;nj++){
        mma16816(F.acc[mi][nj*2+0], a[mi], &bH[nj][0]);
        mma16816(F.acc[mi][nj*2+1], a[mi], &bH[nj][2]);
      }
  }
}

__device__ __forceinline__ void gemm_core(
    uint32_t sb0, int arow0, const uint16_t* __restrict__ Ah,
    const uint16_t* __restrict__ Al, int astride,
    int ch0, const uint16_t* __restrict__ Bh, const uint16_t* __restrict__ Bl,
    int bkoff, int NKC, Frag& F)
{
  const int t = threadIdx.x, lane = t & 31, wid = t >> 5;
  const int wm = (wid & 1)*64, wn = (wid >> 1)*32;
  const uint32_t aoff = (uint32_t)(wm + (lane & 15))*ROWB + ((lane >> 4) & 1)*16;
  const uint32_t boff = (uint32_t)(wn + (lane & 7) + ((lane >> 4) & 1)*8)*ROWB
                      + ((lane >> 3) & 1)*16;
  #pragma unroll
  for (int mi=0;mi<4;mi++)
    #pragma unroll
    for (int ni=0;ni<4;ni++)
      #pragma unroll
      for (int c=0;c<4;c++) F.acc[mi][ni][c] = 0.f;

  #define ISSUE(kc) do { \
    uint32_t sbb = sb0 + ((kc)&1)*BUFB; \
    for (int idx=t; idx<512; idx+=256){ \
      int row = idx >> 2, c = idx & 3; \
      size_t offa = (size_t)(arow0 + row)*astride + (kc)*KC + c*8; \
      size_t offb = (size_t)(ch0 + row)*CF + bkoff + (kc)*KC + c*8; \
      uint32_t so = (uint32_t)row*ROWB + c*16; \
      cp16(sbb + so,         Ah + offa); \
      cp16(sbb + PLANE + so, Al + offa); \
      cp16(sbb + 2*PLANE + so, Bh + offb); \
      cp16(sbb + 3*PLANE + so, Bl + offb); \
    } \
    CP_COMMIT(); \
  } while(0)

  ISSUE(0);
  for (int kc = 0; kc < NKC; kc++){
    if (kc + 1 < NKC){ ISSUE(kc+1); CP_WAIT1(); }
    else             { CP_WAIT0(); }
    __syncthreads();
    mma_chunk(sb0 + (kc&1)*BUFB, aoff, boff, F);
    __syncthreads();
  }
  #undef ISSUE
}

// =====================================================================
__global__ void k_init(){
  int i = blockIdx.x*blockDim.x + threadIdx.x;
  if (i < NFG*C2) g_fg[i] = ENC_NEG_INF;
  if (i < NFG*CO) g_om[i] = ENC_NEG_INF;
}

__global__ __launch_bounds__(256) void k_sort(const int* __restrict__ choice){
  __shared__ int offs[NCLST];
  __shared__ int hist[NCLST];
  const int t = threadIdx.x, b = blockIdx.x;
  const int base = b*NPTS;
  if (t < NCLST){ hist[t] = 0; }
  __syncthreads();
  for (int i=t; i<NPTS; i+=256) atomicAdd(&hist[choice[base+i]], 1);
  __syncthreads();
  if (t == 0){
    int s = 0;
    for (int c=0;c<NCLST;c++){ offs[c] = s; s += hist[c]; }
  }
  __syncthreads();
  for (int i=t; i<NPTS; i+=256){
    int c = choice[base+i];
    int pos = atomicAdd(&offs[c], 1);
    g_perm[base+pos] = base + i;
    g_chs [base+pos] = c;
  }
}

__global__ void k_prep(
    const float* __restrict__ w1, const float* __restrict__ b1,
    const float* __restrict__ bg1, const float* __restrict__ bb1,
    const float* __restrict__ bm1, const float* __restrict__ bv1,
    const float* __restrict__ w2,
    const float* __restrict__ w3,
    const float* __restrict__ b3,
    const float* __restrict__ bg2, const float* __restrict__ bb2,
    const float* __restrict__ bm2, const float* __restrict__ bv2)
{
  int i = blockIdx.x*blockDim.x + threadIdx.x;
  if (i < CF*CF){ uint16_t h,l; split2(w3[i],h,l); g_w3_h[i]=h; g_w3_l[i]=l; }
  int k = i - CF*CF;
  if (k >= 0 && k < C2*C1){ uint16_t h,l; split2(w2[k],h,l); g_w2_h[k]=h; g_w2_l[k]=l; }
  int m = i - CF*CF - C2*C1;
  if (m >= 0 && m < CF){
    float s = bg2[m] * rsqrtf(bv2[m] + 1e-5f);
    g_s2[m] = s;
    g_t2[m] = bb2[m] + (b3[m] - bm2[m]) * s;
  }
  int q = i - CF*CF - C2*C1 - CF;
  if (q >= 0 && q < C1){
    float s = bg1[q] * rsqrtf(bv1[q] + 1e-5f);
    g_w1f[q*4+0] = w1[q*3+0]*s;
    g_w1f[q*4+1] = w1[q*3+1]*s;
    g_w1f[q*4+2] = w1[q*3+2]*s;
    g_w1f[q*4+3] = (b1[q] - bm1[q])*s + bb1[q];
  }
}

// quantize weights: warp-per-row. w3 rows (k 256..512), then w4 rows (k 512)
__global__ __launch_bounds__(256) void k_prepw(const float* __restrict__ w3,
                                               const float* __restrict__ w4){
  const int t = threadIdx.x, lane = t & 31, wid = t >> 5;
  const int id = blockIdx.x*8 + wid;
  if (id < CF){
    const float* src = w3 + (size_t)id*CF + C2;
    float4 v0 = *(const float4*)(src + lane*8);
    float4 v1 = *(const float4*)(src + lane*8 + 4);
    float f[8] = {v0.x,v0.y,v0.z,v0.w,v1.x,v1.y,v1.z,v1.w};
    float m = 0.f;
    #pragma unroll
    for (int i=0;i<8;i++) m = fmaxf(m, fabsf(f[i]));
    #pragma unroll
    for (int o=16;o;o>>=1) m = fmaxf(m, __shfl_xor_sync(0xffffffffu, m, o));
    float inv = m > 0.f ? 127.f/m : 0.f;
    int q1[8], q2[8];
    #pragma unroll
    for (int i=0;i<8;i++) q2e(f[i], inv, q1[i], q2[i]);
    *(uint2*)(g_w3q1 + (size_t)id*C2 + lane*8) =
        make_uint2(pk4(q1[0],q1[1],q1[2],q1[3]), pk4(q1[4],q1[5],q1[6],q1[7]));
    *(uint2*)(g_w3q2 + (size_t)id*C2 + lane*8) =
        make_uint2(pk4(q2[0],q2[1],q2[2],q2[3]), pk4(q2[4],q2[5],q2[6],q2[7]));
    if (lane == 0) g_sB3[id] = m * (1.f/127.f);
  } else if (id < CF + CO){
    int r = id - CF;
    const float* src = w4 + (size_t)r*CF;
    float f[16]; float m = 0.f;
    #pragma unroll
    for (int u=0;u<4;u++){
      float4 v = *(const float4*)(src + lane*16 + u*4);
      f[u*4+0]=v.x; f[u*4+1]=v.y; f[u*4+2]=v.z; f[u*4+3]=v.w;
    }
    #pragma unroll
    for (int i=0;i<16;i++) m = fmaxf(m, fabsf(f[i]));
    #pragma unroll
    for (int o=16;o;o>>=1) m = fmaxf(m, __shfl_xor_sync(0xffffffffu, m, o));
    float inv = m > 0.f ? 127.f/m : 0.f;
    int q1[16], q2[16];
    #pragma unroll
    for (int i=0;i<16;i++) q2e(f[i], inv, q1[i], q2[i]);
    uint4 p1, p2;
    p1.x = pk4(q1[0],q1[1],q1[2],q1[3]);   p1.y = pk4(q1[4],q1[5],q1[6],q1[7]);
    p1.z = pk4(q1[8],q1[9],q1[10],q1[11]); p1.w = pk4(q1[12],q1[13],q1[14],q1[15]);
    p2.x = pk4(q2[0],q2[1],q2[2],q2[3]);   p2.y = pk4(q2[4],q2[5],q2[6],q2[7]);
    p2.z = pk4(q2[8],q2[9],q2[10],q2[11]); p2.w = pk4(q2[12],q2[13],q2[14],q2[15]);
    *(uint4*)(g_w4q1 + (size_t)r*CF + lane*16) = p1;
    *(uint4*)(g_w4q2 + (size_t)r*CF + lane*16) = p2;
    if (lane == 0) g_sB4[r] = m * (1.f/127.f);
  }
}

// =====================================================================
// Stage 1 (bf16 HMMA, sorted points) — unchanged from round 8
// =====================================================================
__global__ __launch_bounds__(256) void k_stage1(
    const float* __restrict__ xyz, const float* __restrict__ b2)
{
  extern __shared__ char smem[];
  __shared__ float sx[128][3];
  __shared__ int   scl[128];
  __shared__ int   sperm[128];

  const int t = threadIdx.x, lane = t & 31, wid = t >> 5;
  const int p0 = blockIdx.x*128, bb = blockIdx.x >> 6;
  const int ch0 = blockIdx.y*128;

  for (int i=t; i<128; i+=256){ scl[i] = g_chs[p0+i]; sperm[i] = g_perm[p0+i]; }
  __syncthreads();
  for (int i=t; i<128*3; i+=256) sx[i/3][i%3] = xyz[(size_t)sperm[i/3]*3 + (i%3)];
  __syncthreads();

  const uint32_t sb = smem_u32(smem);
  uint16_t* pAh = (uint16_t*)smem;
  uint16_t* pAl = (uint16_t*)(smem + PLANE);

  const int wm = (wid & 1)*64, wn = (wid >> 1)*32;
  const uint32_t aoff = (uint32_t)(wm + (lane & 15))*ROWB + ((lane >> 4) & 1)*16;
  const uint32_t boff = (uint32_t)(wn + (lane & 7) + ((lane >> 4) & 1)*8)*ROWB
                      + ((lane >> 3) & 1)*16;

  Frag F;
  #pragma unroll
  for (int mi=0;mi<4;mi++)
    #pragma unroll
    for (int ni=0;ni<4;ni++)
      #pragma unroll
      for (int c=0;c<4;c++) F.acc[mi][ni][c] = 0.f;

  for (int kc=0; kc<4; kc++){
    for (int idx=t; idx<512; idx+=256){
      int row = idx >> 2, c = idx & 3;
      size_t off = (size_t)(ch0+row)*C1 + kc*KC + c*8;
      uint32_t so = (uint32_t)row*ROWB + c*16;
      cp16(sb + 2*PLANE + so, g_w2_h + off);
      cp16(sb + 3*PLANE + so, g_w2_l + off);
    }
    CP_COMMIT();
    for (int idx=t; idx<4096; idx+=256){
      int row = idx >> 5, kp = idx & 31;
      int k = kc*KC + kp;
      float4 wf = *(const float4*)(g_w1f + 4*k);
      float h = fmaf(sx[row][0], wf.x, fmaf(sx[row][1], wf.y, fmaf(sx[row][2], wf.z, wf.w)));
      h = fmaxf(h, 0.f);
      uint16_t hh, hl; split2(h, hh, hl);
      uint32_t so = (uint32_t)row*(ROWB/2) + kp;
      pAh[so] = hh; pAl[so] = hl;
    }
    CP_WAIT0();
    __syncthreads();
    mma_chunk(sb, aoff, boff, F);
    __syncthreads();
  }

  float* Sv = (float*)smem;
  const int r0 = lane >> 2, cp = (lane & 3)*2;
  #pragma unroll
  for (int mi=0;mi<4;mi++){
    int pa = wm + mi*16 + r0;
    size_t ga = (size_t)(p0 + pa), gb = ga + 8;
    #pragma unroll
    for (int ni=0;ni<4;ni++){
      int chl = wn + ni*8 + cp;
      int ch  = ch0 + chl;
      float b0 = b2[ch], b1v = b2[ch+1];
      float x0 = F.acc[mi][ni][0] + b0, x1 = F.acc[mi][ni][1] + b1v;
      float y0 = F.acc[mi][ni][2] + b0, y1 = F.acc[mi][ni][3] + b1v;
      uint16_t h0,l0,h1,l1;
      split2(x0,h0,l0); split2(x1,h1,l1);
      *(uint32_t*)(g_feat_h + ga*C2 + ch) = (uint32_t)h0 | ((uint32_t)h1<<16);
      *(uint32_t*)(g_feat_l + ga*C2 + ch) = (uint32_t)l0 | ((uint32_t)l1<<16);
      split2(y0,h0,l0); split2(y1,h1,l1);
      *(uint32_t*)(g_feat_h + gb*C2 + ch) = (uint32_t)h0 | ((uint32_t)h1<<16);
      *(uint32_t*)(g_feat_l + gb*C2 + ch) = (uint32_t)l0 | ((uint32_t)l1<<16);
      Sv[(size_t)pa*SVSTR1 + chl]       = x0;
      Sv[(size_t)pa*SVSTR1 + chl + 1]   = x1;
      Sv[(size_t)(pa+8)*SVSTR1 + chl]   = y0;
      Sv[(size_t)(pa+8)*SVSTR1 + chl+1] = y1;
    }
  }
  __syncthreads();

  {
    const int ch = t & 127, half = t >> 7;
    int r = half*64;
    int cprev = scl[r];
    float run = __int_as_float(0xff800000);
    unsigned* fgb = &g_fg[(size_t)bb*NCLST*C2 + ch0 + ch];
    for (int i=0;i<64;i++,r++){
      int c = scl[r];
      if (c != cprev){
        atomicMax(&fgb[(size_t)cprev*C2], enc(run));
        run = __int_as_float(0xff800000);
        cprev = c;
      }
      run = fmaxf(run, Sv[(size_t)r*SVSTR1 + ch]);
    }
    atomicMax(&fgb[(size_t)cprev*C2], enc(run));
  }
}

__global__ void k_fg_split(){
  int i = blockIdx.x*blockDim.x + threadIdx.x;
  if (i < NFG*C2){
    uint16_t h,l; split2(dec(g_fg[i]), h, l);
    g_fg_h[i] = h; g_fg_l[i] = l;
  }
}

// quantize feat rows (256 wide): warp per row
__global__ __launch_bounds__(256) void k_quantF(){
  const int t = threadIdx.x, lane = t & 31, wid = t >> 5;
  const int row = blockIdx.x*8 + wid;
  const uint32_t* ph = (const uint32_t*)(g_feat_h + (size_t)row*C2);
  const uint32_t* pl = (const uint32_t*)(g_feat_l + (size_t)row*C2);
  uint4 vh = *(const uint4*)(ph + lane*4);
  uint4 vl = *(const uint4*)(pl + lane*4);
  float f[8];
  bpair(vh.x, vl.x, f[0], f[1]);
  bpair(vh.y, vl.y, f[2], f[3]);
  bpair(vh.z, vl.z, f[4], f[5]);
  bpair(vh.w, vl.w, f[6], f[7]);
  float m = 0.f;
  #pragma unroll
  for (int i=0;i<8;i++) m = fmaxf(m, fabsf(f[i]));
  #pragma unroll
  for (int o=16;o;o>>=1) m = fmaxf(m, __shfl_xor_sync(0xffffffffu, m, o));
  float inv = m > 0.f ? 127.f/m : 0.f;
  int q1[8], q2[8];
  #pragma unroll
  for (int i=0;i<8;i++) q2e(f[i], inv, q1[i], q2[i]);
  *(uint2*)(g_q1f + (size_t)row*C2 + lane*8) =
      make_uint2(pk4(q1[0],q1[1],q1[2],q1[3]), pk4(q1[4],q1[5],q1[6],q1[7]));
  *(uint2*)(g_q2f + (size_t)row*C2 + lane*8) =
      make_uint2(pk4(q2[0],q2[1],q2[2],q2[3]), pk4(q2[4],q2[5],q2[6],q2[7]));
  if (lane == 0) g_sAf[row] = m * (1.f/127.f);
}

// quantize h2 rows (512 wide): warp per row
__global__ __launch_bounds__(256) void k_quantH(){
  const int t = threadIdx.x, lane = t & 31, wid = t >> 5;
  const int row = blockIdx.x*8 + wid;
  const uint32_t* ph = (const uint32_t*)(g_h2_h + (size_t)row*CF);
  const uint32_t* pl = (const uint32_t*)(g_h2_l + (size_t)row*CF);
  uint4 vh0 = *(const uint4*)(ph + lane*8);
  uint4 vh1 = *(const uint4*)(ph + lane*8 + 4);
  uint4 vl0 = *(const uint4*)(pl + lane*8);
  uint4 vl1 = *(const uint4*)(pl + lane*8 + 4);
  float f[16];
  bpair(vh0.x, vl0.x, f[0], f[1]);   bpair(vh0.y, vl0.y, f[2], f[3]);
  bpair(vh0.z, vl0.z, f[4], f[5]);   bpair(vh0.w, vl0.w, f[6], f[7]);
  bpair(vh1.x, vl1.x, f[8], f[9]);   bpair(vh1.y, vl1.y, f[10], f[11]);
  bpair(vh1.z, vl1.z, f[12], f[13]); bpair(vh1.w, vl1.w, f[14], f[15]);
  float m = 0.f;
  #pragma unroll
  for (int i=0;i<16;i++) m = fmaxf(m, fabsf(f[i]));
  #pragma unroll
  for (int o=16;o;o>>=1) m = fmaxf(m, __shfl_xor_sync(0xffffffffu, m, o));
  float inv = m > 0.f ? 127.f/m : 0.f;
  int q1[16], q2[16];
  #pragma unroll
  for (int i=0;i<16;i++) q2e(f[i], inv, q1[i], q2[i]);
  uint4 p1, p2;
  p1.x = pk4(q1[0],q1[1],q1[2],q1[3]);   p1.y = pk4(q1[4],q1[5],q1[6],q1[7]);
  p1.z = pk4(q1[8],q1[9],q1[10],q1[11]); p1.w = pk4(q1[12],q1[13],q1[14],q1[15]);
  p2.x = pk4(q2[0],q2[1],q2[2],q2[3]);   p2.y = pk4(q2[4],q2[5],q2[6],q2[7]);
  p2.z = pk4(q2[8],q2[9],q2[10],q2[11]); p2.w = pk4(q2[12],q2[13],q2[14],q2[15]);
  *(uint4*)(g_q1h + (size_t)row*CF + lane*16) = p1;
  *(uint4*)(g_q2h + (size_t)row*CF + lane*16) = p2;
  if (lane == 0) g_sAh[row] = m * (1.f/127.f);
}

// =====================================================================
// Cluster GEMM (bf16): G = fg @ w3[:, :256]^T   grid (16, 4)
// =====================================================================
__global__ __launch_bounds__(256) void k_gemmC()
{
  extern __shared__ char smem[];
  const int t = threadIdx.x, lane = t & 31, wid = t >> 5;
  const int r0b = blockIdx.x*128;
  const int ch0 = blockIdx.y*128;

  Frag F;
  gemm_core(smem_u32(smem), r0b, g_fg_h, g_fg_l, C2, ch0, g_w3_h, g_w3_l, 0, C2/KC, F);

  const int wm = (wid & 1)*64, wn = (wid >> 1)*32;
  const int r0 = lane >> 2, cp = (lane & 3)*2;
  #pragma unroll
  for (int mi=0;mi<4;mi++){
    size_t ga = (size_t)(r0b + wm + mi*16 + r0), gb = ga + 8;
    #pragma unroll
    for (int ni=0;ni<4;ni++){
      int ch = ch0 + wn + ni*8 + cp;
      *(float2*)(g_G + ga*CF + ch) = make_float2(F.acc[mi][ni][0], F.acc[mi][ni][1]);
      *(float2*)(g_G + gb*CF + ch) = make_float2(F.acc[mi][ni][2], F.acc[mi][ni][3]);
    }
  }
}

// =====================================================================
// int8 split GEMM core: CTA 128 pts x 64 ch, warp tile 32x32 (8 warps 4x2)
// =====================================================================
__device__ __forceinline__ void mma_chunk_i8(uint32_t sb, uint32_t aoff, uint32_t boff,
                                             int acc1[2][4][4], int acc2[2][4][4]){
  const uint32_t A1 = sb, A2 = sb + PLANE_A, B1 = sb + 2*PLANE_A, B2 = sb + 2*PLANE_A + PLANE_B;
  #pragma unroll
  for (int ks=0; ks<2; ks++){
    const uint32_t kb = ks*32;
    uint32_t a[2][4], b1[2][4], b2[2][4];
    #pragma unroll
    for (int mi=0;mi<2;mi++) ldsm4(a[mi], A1 + aoff + mi*(16*ROWB) + kb);
    #pragma unroll
    for (int g=0;g<2;g++)    ldsm4(b1[g], B1 + boff + g*(16*ROWB) + kb);
    #pragma unroll
    for (int mi=0;mi<2;mi++)
      #pragma unroll
      for (int g=0;g<2;g++){
        mma_s8(acc1[mi][g*2+0], a[mi], &b1[g][0]);
        mma_s8(acc1[mi][g*2+1], a[mi], &b1[g][2]);
      }
    #pragma unroll
    for (int g=0;g<2;g++)    ldsm4(b2[g], B2 + boff + g*(16*ROWB) + kb);
    #pragma unroll
    for (int mi=0;mi<2;mi++)
      #pragma unroll
      for (int g=0;g<2;g++){
        mma_s8(acc2[mi][g*2+0], a[mi], &b2[g][0]);
        mma_s8(acc2[mi][g*2+1], a[mi], &b2[g][2]);
      }
    #pragma unroll
    for (int mi=0;mi<2;mi++) ldsm4(a[mi], A2 + aoff + mi*(16*ROWB) + kb);
    #pragma unroll
    for (int mi=0;mi<2;mi++)
      #pragma unroll
      for (int g=0;g<2;g++){
        mma_s8(acc2[mi][g*2+0], a[mi], &b1[g][0]);
        mma_s8(acc2[mi][g*2+1], a[mi], &b1[g][2]);
      }
  }
}

__device__ __forceinline__ void gemm_core_i8(
    uint32_t sb0, int arow0, const int8_t* __restrict__ Aq1,
    const int8_t* __restrict__ Aq2, int astride,
    int ch0, const int8_t* __restrict__ Bq1, const int8_t* __restrict__ Bq2,
    int bstride, int NKC, int acc1[2][4][4], int acc2[2][4][4])
{
  const int t = threadIdx.x, lane = t & 31, wid = t >> 5;
  const int wm = (wid >> 1)*32, wn = (wid & 1)*32;
  const uint32_t aoff = (uint32_t)(wm + (lane & 15))*ROWB + ((lane >> 4) & 1)*16;
  const uint32_t boff = (uint32_t)(wn + (lane & 7) + ((lane >> 4) & 1)*8)*ROWB
                      + ((lane >> 3) & 1)*16;
  #pragma unroll
  for (int mi=0;mi<2;mi++)
    #pragma unroll
    for (int nj=0;nj<4;nj++)
      #pragma unroll
      for (int c=0;c<4;c++){ acc1[mi][nj][c] = 0; acc2[mi][nj][c] = 0; }

  #define ISSUE8(kc) do { \
    uint32_t sbb = sb0 + ((kc)&1)*BUF_I8; \
    for (int idx=t; idx<512; idx+=256){ \
      int row = idx >> 2, c = idx & 3; \
      size_t offa = (size_t)(arow0 + row)*astride + (kc)*64 + c*16; \
      uint32_t so = (uint32_t)row*ROWB + c*16; \
      cp16(sbb + so,           Aq1 + offa); \
      cp16(sbb + PLANE_A + so, Aq2 + offa); \
    } \
    for (int idx=t; idx<256; idx+=256){ \
      int row = idx >> 2, c = idx & 3; \
      size_t offb = (size_t)(ch0 + row)*bstride + (kc)*64 + c*16; \
      uint32_t so = (uint32_t)row*ROWB + c*16; \
      cp16(sbb + 2*PLANE_A + so,           Bq1 + offb); \
      cp16(sbb + 2*PLANE_A + PLANE_B + so, Bq2 + offb); \
    } \
    CP_COMMIT(); \
  } while(0)

  ISSUE8(0);
  for (int kc = 0; kc < NKC; kc++){
    if (kc + 1 < NKC){ ISSUE8(kc+1); CP_WAIT1(); }
    else             { CP_WAIT0(); }
    __syncthreads();
    mma_chunk_i8(sb0 + (kc&1)*BUF_I8, aoff, boff, acc1, acc2);
    __syncthreads();
  }
  #undef ISSUE8
}

#define INV256 0.00390625f

// GEMM2 int8: h2 = relu(bn2(feat@w3b^T + G[cluster])) -> h2 planes
// grid (2048, 8)
__global__ __launch_bounds__(256, 2) void k_gemm2()
{
  extern __shared__ char smem[];
  __shared__ int scl[128];
  const int t = threadIdx.x, lane = t & 31, wid = t >> 5;
  const int p0 = blockIdx.x*128, bb = blockIdx.x >> 6;
  const int ch0 = blockIdx.y*64;

  for (int i=t; i<128; i+=256) scl[i] = g_chs[p0+i];
  __syncthreads();

  int acc1[2][4][4], acc2[2][4][4];
  gemm_core_i8(smem_u32(smem), p0, g_q1f, g_q2f, C2, ch0, g_w3q1, g_w3q2, C2,
               C2/64, acc1, acc2);

  const int wm = (wid >> 1)*32, wn = (wid & 1)*32;
  const int r0 = lane >> 2, cp = (lane & 3)*2;
  #pragma unroll
  for (int mi=0;mi<2;mi++){
    int m0 = wm + mi*16 + r0, m1 = m0 + 8;
    size_t ga = (size_t)(p0 + m0), gb = (size_t)(p0 + m1);
    float sA0 = g_sAf[ga], sA1 = g_sAf[gb];
    const float* Ga = g_G + (size_t)(bb*NCLST + scl[m0])*CF;
    const float* Gb = g_G + (size_t)(bb*NCLST + scl[m1])*CF;
    #pragma unroll
    for (int nj=0;nj<4;nj++){
      int chl = wn + nj*8 + cp;
      int ch  = ch0 + chl;
      float sb0 = g_sB3[ch], sb1 = g_sB3[ch+1];
      float v00 = ((float)acc1[mi][nj][0] + (float)acc2[mi][nj][0]*INV256)*(sA0*sb0) + Ga[ch];
      float v01 = ((float)acc1[mi][nj][1] + (float)acc2[mi][nj][1]*INV256)*(sA0*sb1) + Ga[ch+1];
      float v10 = ((float)acc1[mi][nj][2] + (float)acc2[mi][nj][2]*INV256)*(sA1*sb0) + Gb[ch];
      float v11 = ((float)acc1[mi][nj][3] + (float)acc2[mi][nj][3]*INV256)*(sA1*sb1) + Gb[ch+1];
      float x0 = fmaxf(fmaf(v00, g_s2[ch],   g_t2[ch]),   0.f);
      float x1 = fmaxf(fmaf(v01, g_s2[ch+1], g_t2[ch+1]), 0.f);
      float y0 = fmaxf(fmaf(v10, g_s2[ch],   g_t2[ch]),   0.f);
      float y1 = fmaxf(fmaf(v11, g_s2[ch+1], g_t2[ch+1]), 0.f);
      uint16_t h0,l0,h1,l1;
      split2(x0,h0,l0); split2(x1,h1,l1);
      *(uint32_t*)(g_h2_h + ga*CF + ch) = (uint32_t)h0 | ((uint32_t)h1<<16);
      *(uint32_t*)(g_h2_l + ga*CF + ch) = (uint32_t)l0 | ((uint32_t)l1<<16);
      split2(y0,h0,l0); split2(y1,h1,l1);
      *(uint32_t*)(g_h2_h + gb*CF + ch) = (uint32_t)h0 | ((uint32_t)h1<<16);
      *(uint32_t*)(g_h2_l + gb*CF + ch) = (uint32_t)l0 | ((uint32_t)l1<<16);
    }
  }
}

// GEMM3 int8: out = h2@w4^T + b4 -> segment-reduced cluster max
// grid (2048, 6)
__global__ __launch_bounds__(256, 2) void k_gemm3(const float* __restrict__ b4)
{
  extern __shared__ char smem[];
  __shared__ int scl[128];
  const int t = threadIdx.x, lane = t & 31, wid = t >> 5;
  const int p0 = blockIdx.x*128, bb = blockIdx.x >> 6;
  const int ch0 = blockIdx.y*64;

  for (int i=t; i<128; i+=256) scl[i] = g_chs[p0+i];
  __syncthreads();

  int acc1[2][4][4], acc2[2][4][4];
  gemm_core_i8(smem_u32(smem), p0, g_q1h, g_q2h, CF, ch0, g_w4q1, g_w4q2, CF,
               CF/64, acc1, acc2);

  float* Sv = (float*)smem;
  const int wm = (wid >> 1)*32, wn = (wid & 1)*32;
  const int r0 = lane >> 2, cp = (lane & 3)*2;
  #pragma unroll
  for (int mi=0;mi<2;mi++){
    int m0 = wm + mi*16 + r0, m1 = m0 + 8;
    float sA0 = g_sAh[p0 + m0], sA1 = g_sAh[p0 + m1];
    #pragma unroll
    for (int nj=0;nj<4;nj++){
      int chl = wn + nj*8 + cp;
      int ch  = ch0 + chl;
      float sb0 = g_sB4[ch], sb1 = g_sB4[ch+1];
      float bb0 = b4[ch], bb1 = b4[ch+1];
      Sv[(size_t)m0*SVSTR3 + chl]     = ((float)acc1[mi][nj][0] + (float)acc2[mi][nj][0]*INV256)*(sA0*sb0) + bb0;
      Sv[(size_t)m0*SVSTR3 + chl + 1] = ((float)acc1[mi][nj][1] + (float)acc2[mi][nj][1]*INV256)*(sA0*sb1) + bb1;
      Sv[(size_t)m1*SVSTR3 + chl]     = ((float)acc1[mi][nj][2] + (float)acc2[mi][nj][2]*INV256)*(sA1*sb0) + bb0;
      Sv[(size_t)m1*SVSTR3 + chl + 1] = ((float)acc1[mi][nj][3] + (float)acc2[mi][nj][3]*INV256)*(sA1*sb1) + bb1;
    }
  }
  __syncthreads();

  {
    const int ch = t & 63, grp = t >> 6;
    int r = grp*32;
    int cprev = scl[r];
    float run = __int_as_float(0xff800000);
    unsigned* omb = &g_om[(size_t)bb*NCLST*CO + ch0 + ch];
    for (int i=0;i<32;i++,r++){
      int c = scl[r];
      if (c != cprev){
        atomicMax(&omb[(size_t)cprev*CO], enc(run));
        run = __int_as_float(0xff800000);
        cprev = c;
      }
      run = fmaxf(run, Sv[(size_t)r*SVSTR3 + ch]);
    }
    atomicMax(&omb[(size_t)cprev*CO], enc(run));
  }
}

__global__ void k_final(float* __restrict__ out){
  int i = blockIdx.x*blockDim.x + threadIdx.x;
  if (i < NFG*CO) out[i] = dec(g_om[i]);
}

// =====================================================================
extern "C" void kernel_launch(void* const* d_in, const int* in_sizes, int n_in,
                              void* d_out, int out_size)
{
  const float* xyz    = (const float*)d_in[0];
  const int*   choice = (const int*)  d_in[1];
  const float* w1  = (const float*)d_in[2];
  const float* b1  = (const float*)d_in[3];
  const float* g1  = (const float*)d_in[4];
  const float* bb1 = (const float*)d_in[5];
  const float* m1  = (const float*)d_in[6];
  const float* v1  = (const float*)d_in[7];
  const float* w2  = (const float*)d_in[8];
  const float* b2  = (const float*)d_in[9];
  const float* w3  = (const float*)d_in[10];
  const float* b3  = (const float*)d_in[11];
  const float* g2  = (const float*)d_in[12];
  const float* bb2 = (const float*)d_in[13];
  const float* m2  = (const float*)d_in[14];
  const float* v2  = (const float*)d_in[15];
  const float* w4  = (const float*)d_in[16];
  const float* b4  = (const float*)d_in[17];

  size_t smem1  = SVB1;        // 66560
  size_t smemC  = 2*BUFB;      // 81920
  size_t smemI8 = 2*BUF_I8;    // 61440
  cudaFuncSetAttribute(k_stage1, cudaFuncAttributeMaxDynamicSharedMemorySize, (int)smem1);
  cudaFuncSetAttribute(k_gemmC,  cudaFuncAttributeMaxDynamicSharedMemorySize, (int)smemC);
  cudaFuncSetAttribute(k_gemm2,  cudaFuncAttributeMaxDynamicSharedMemorySize, (int)smemI8);
  cudaFuncSetAttribute(k_gemm3,  cudaFuncAttributeMaxDynamicSharedMemorySize, (int)smemI8);

  int ntot  = NFG*CO;
  int nprep = CF*CF + C2*C1 + CF + C1;

  k_init   <<<(ntot+255)/256, 256>>>();
  k_sort   <<<BATCH, 256>>>(choice);
  k_prep   <<<(nprep+255)/256, 256>>>(w1,b1,g1,bb1,m1,v1,w2, w3,b3,g2,bb2,m2,v2);
  k_prepw  <<<(CF+CO+7)/8, 256>>>(w3, w4);
  {
    dim3 g1d(PTOT/128, C2/128);   // (2048, 2)
    k_stage1<<<g1d, 256, smem1>>>(xyz, b2);
  }
  k_quantF <<<PTOT/8, 256>>>();
  k_fg_split<<<(NFG*C2+255)/256, 256>>>();
  {
    dim3 gcd(NFG/128, CF/128);    // (16, 4)
    k_gemmC<<<gcd, 256, smemC>>>();
    dim3 g2d(PTOT/128, CF/64);    // (2048, 8)
    k_gemm2<<<g2d, 256, smemI8>>>();
  }
  k_quantH <<<PTOT/8, 256>>>();
  {
    dim3 g3d(PTOT/128, CO/64);    // (2048, 6)
    k_gemm3<<<g3d, 256, smemI8>>>(b4);
  }
  k_final  <<<(ntot+255)/256, 256>>>((float*)d_out);
}

// round 10
// speedup vs baseline: 2.1012x; 2.1012x over previous
#include <cuda_runtime.h>
#include <cuda_bf16.h>
#include <stdint.h>

#define BATCH 32
#define NPTS  8192
#define NCLST 64
#define C1    128
#define C2    256
#define CF    512
#define CO    384
#define PTOT  (BATCH*NPTS)
#define NFG   (BATCH*NCLST)
#define ENC_NEG_INF 0x007FFFFFu

#define ROWB   80
#define PLANE  (128*ROWB)       // 10240 B
#define BUFB   (4*PLANE)        // 40960 B
#define KC     32
#define SVSTR  130              // f32 stride of epilogue tile
#define SVB    (128*SVSTR*4)    // 66560 B

// ---------------- scratch ----------------
__device__ unsigned g_fg[NFG*C2];
__device__ unsigned g_om[NFG*CO];
__device__ int g_perm[PTOT];
__device__ int g_chs[PTOT];
__device__ __align__(16) uint16_t g_h_h[(size_t)PTOT*C1];    // layer-1 activations (sorted)
__device__ __align__(16) uint16_t g_h_l[(size_t)PTOT*C1];
__device__ __align__(16) uint16_t g_feat_h[(size_t)PTOT*C2];
__device__ __align__(16) uint16_t g_feat_l[(size_t)PTOT*C2];
__device__ __align__(16) uint16_t g_fg_h[NFG*C2];
__device__ __align__(16) uint16_t g_fg_l[NFG*C2];
__device__ __align__(16) uint16_t g_h2_h[(size_t)PTOT*CF];
__device__ __align__(16) uint16_t g_h2_l[(size_t)PTOT*CF];
__device__ __align__(16) uint16_t g_w2_h[C2*C1], g_w2_l[C2*C1];
__device__ __align__(16) uint16_t g_w3_h[CF*CF], g_w3_l[CF*CF];
__device__ __align__(16) uint16_t g_w4_h[CO*CF], g_w4_l[CO*CF];
__device__ float g_G[(size_t)NFG*CF];
__device__ float g_s2[CF], g_t2[CF];
__device__ __align__(16) float g_w1f[C1*4];

// ---------------- helpers ----------------
__device__ __forceinline__ unsigned enc(float f){
  unsigned u = __float_as_uint(f);
  return (u & 0x80000000u) ? ~u : (u | 0x80000000u);
}
__device__ __forceinline__ float dec(unsigned u){
  u = (u & 0x80000000u) ? (u & 0x7FFFFFFFu) : ~u;
  return __uint_as_float(u);
}
__device__ __forceinline__ void split2(float v, uint16_t& h, uint16_t& l){
  __nv_bfloat16 bh = __float2bfloat16(v);
  float r = v - __bfloat162float(bh);
  if (!(r == r)) r = 0.f;
  h = __bfloat16_as_ushort(bh);
  l = __bfloat16_as_ushort(__float2bfloat16(r));
}
__device__ __forceinline__ uint32_t smem_u32(const void* p){
  uint32_t a;
  asm("{ .reg .u64 t; cvta.to.shared.u64 t, %1; cvt.u32.u64 %0, t; }" : "=r"(a) : "l"(p));
  return a;
}
__device__ __forceinline__ void cp16(uint32_t dst, const void* src){
  asm volatile("cp.async.cg.shared.global [%0], [%1], 16;" :: "r"(dst), "l"(src));
}
#define CP_COMMIT() asm volatile("cp.async.commit_group;" ::: "memory")
#define CP_WAIT1()  asm volatile("cp.async.wait_group 1;"  ::: "memory")
#define CP_WAIT0()  asm volatile("cp.async.wait_group 0;"  ::: "memory")

__device__ __forceinline__ void ldsm4(uint32_t* r, uint32_t addr){
  asm volatile("ldmatrix.sync.aligned.m8n8.x4.shared.b16 {%0,%1,%2,%3}, [%4];"
    : "=r"(r[0]),"=r"(r[1]),"=r"(r[2]),"=r"(r[3]) : "r"(addr));
}
__device__ __forceinline__ void mma16816(float* c, const uint32_t* a, const uint32_t* b){
  asm volatile("mma.sync.aligned.m16n8k16.row.col.f32.bf16.bf16.f32 "
    "{%0,%1,%2,%3}, {%4,%5,%6,%7}, {%8,%9}, {%0,%1,%2,%3};"
    : "+f"(c[0]),"+f"(c[1]),"+f"(c[2]),"+f"(c[3])
    : "r"(a[0]),"r"(a[1]),"r"(a[2]),"r"(a[3]), "r"(b[0]),"r"(b[1]));
}

struct Frag { float acc[4][4][4]; };

__device__ __forceinline__ void mma_chunk(uint32_t sb, uint32_t aoff, uint32_t boff, Frag& F){
  const uint32_t aAh = sb, aAl = sb + PLANE, aBh = sb + 2*PLANE, aBl = sb + 3*PLANE;
  #pragma unroll
  for (int ks = 0; ks < 2; ks++){
    const uint32_t kb = ks * 32;
    uint32_t a[4][4], bH[2][4], bL[2][4];
    #pragma unroll
    for (int mi=0;mi<4;mi++) ldsm4(a[mi],  aAh + aoff + mi*(16*ROWB) + kb);
    #pragma unroll
    for (int nj=0;nj<2;nj++) ldsm4(bH[nj], aBh + boff + nj*(16*ROWB) + kb);
    #pragma unroll
    for (int mi=0;mi<4;mi++)
      #pragma unroll
      for (int nj=0;nj<2;nj++){
        mma16816(F.acc[mi][nj*2+0], a[mi], &bH[nj][0]);
        mma16816(F.acc[mi][nj*2+1], a[mi], &bH[nj][2]);
      }
    #pragma unroll
    for (int nj=0;nj<2;nj++) ldsm4(bL[nj], aBl + boff + nj*(16*ROWB) + kb);
    #pragma unroll
    for (int mi=0;mi<4;mi++)
      #pragma unroll
      for (int nj=0;nj<2;nj++){
        mma16816(F.acc[mi][nj*2+0], a[mi], &bL[nj][0]);
        mma16816(F.acc[mi][nj*2+1], a[mi], &bL[nj][2]);
      }
    #pragma unroll
    for (int mi=0;mi<4;mi++) ldsm4(a[mi], aAl + aoff + mi*(16*ROWB) + kb);
    #pragma unroll
    for (int mi=0;mi<4;mi++)
      #pragma unroll
      for (int nj=0;nj<2;nj++){
        mma16816(F.acc[mi][nj*2+0], a[mi], &bH[nj][0]);
        mma16816(F.acc[mi][nj*2+1], a[mi], &bH[nj][2]);
      }
  }
}

// double-buffered 128x128 gemm core (linear A reads, B row-stride param)
__device__ __forceinline__ void gemm_core(
    uint32_t sb0, int arow0, const uint16_t* __restrict__ Ah,
    const uint16_t* __restrict__ Al, int astride,
    int ch0, const uint16_t* __restrict__ Bh, const uint16_t* __restrict__ Bl,
    int bstride, int bkoff, int NKC, Frag& F)
{
  const int t = threadIdx.x, lane = t & 31, wid = t >> 5;
  const int wm = (wid & 1)*64, wn = (wid >> 1)*32;
  const uint32_t aoff = (uint32_t)(wm + (lane & 15))*ROWB + ((lane >> 4) & 1)*16;
  const uint32_t boff = (uint32_t)(wn + (lane & 7) + ((lane >> 4) & 1)*8)*ROWB
                      + ((lane >> 3) & 1)*16;

  #pragma unroll
  for (int mi=0;mi<4;mi++)
    #pragma unroll
    for (int ni=0;ni<4;ni++)
      #pragma unroll
      for (int c=0;c<4;c++) F.acc[mi][ni][c] = 0.f;

  #define ISSUE(kc) do { \
    uint32_t sbb = sb0 + ((kc)&1)*BUFB; \
    for (int idx=t; idx<512; idx+=256){ \
      int row = idx >> 2, c = idx & 3; \
      size_t offa = (size_t)(arow0 + row)*astride + (kc)*KC + c*8; \
      size_t offb = (size_t)(ch0 + row)*bstride + bkoff + (kc)*KC + c*8; \
      uint32_t so = (uint32_t)row*ROWB + c*16; \
      cp16(sbb + so,         Ah + offa); \
      cp16(sbb + PLANE + so, Al + offa); \
      cp16(sbb + 2*PLANE + so, Bh + offb); \
      cp16(sbb + 3*PLANE + so, Bl + offb); \
    } \
    CP_COMMIT(); \
  } while(0)

  ISSUE(0);
  for (int kc = 0; kc < NKC; kc++){
    if (kc + 1 < NKC){ ISSUE(kc+1); CP_WAIT1(); }
    else             { CP_WAIT0(); }
    __syncthreads();
    mma_chunk(sb0 + (kc&1)*BUFB, aoff, boff, F);
    __syncthreads();
  }
  #undef ISSUE
}

// =====================================================================
__global__ void k_init(){
  int i = blockIdx.x*blockDim.x + threadIdx.x;
  if (i < NFG*C2) g_fg[i] = ENC_NEG_INF;
  if (i < NFG*CO) g_om[i] = ENC_NEG_INF;
}

__global__ __launch_bounds__(256) void k_sort(const int* __restrict__ choice){
  __shared__ int offs[NCLST];
  __shared__ int hist[NCLST];
  const int t = threadIdx.x, b = blockIdx.x;
  const int base = b*NPTS;
  if (t < NCLST){ hist[t] = 0; }
  __syncthreads();
  for (int i=t; i<NPTS; i+=256) atomicAdd(&hist[choice[base+i]], 1);
  __syncthreads();
  if (t == 0){
    int s = 0;
    for (int c=0;c<NCLST;c++){ offs[c] = s; s += hist[c]; }
  }
  __syncthreads();
  for (int i=t; i<NPTS; i+=256){
    int c = choice[base+i];
    int pos = atomicAdd(&offs[c], 1);
    g_perm[base+pos] = base + i;
    g_chs [base+pos] = c;
  }
}

__global__ void k_prep(
    const float* __restrict__ w1, const float* __restrict__ b1,
    const float* __restrict__ bg1, const float* __restrict__ bb1,
    const float* __restrict__ bm1, const float* __restrict__ bv1,
    const float* __restrict__ w2,
    const float* __restrict__ w3, const float* __restrict__ w4,
    const float* __restrict__ b3,
    const float* __restrict__ bg2, const float* __restrict__ bb2,
    const float* __restrict__ bm2, const float* __restrict__ bv2)
{
  int i = blockIdx.x*blockDim.x + threadIdx.x;
  if (i < CF*CF){ uint16_t h,l; split2(w3[i],h,l); g_w3_h[i]=h; g_w3_l[i]=l; }
  int j = i - CF*CF;
  if (j >= 0 && j < CO*CF){ uint16_t h,l; split2(w4[j],h,l); g_w4_h[j]=h; g_w4_l[j]=l; }
  int k = i - CF*CF - CO*CF;
  if (k >= 0 && k < C2*C1){ uint16_t h,l; split2(w2[k],h,l); g_w2_h[k]=h; g_w2_l[k]=l; }
  int m = i - CF*CF - CO*CF - C2*C1;
  if (m >= 0 && m < CF){
    float s = bg2[m] * rsqrtf(bv2[m] + 1e-5f);
    g_s2[m] = s;
    g_t2[m] = bb2[m] + (b3[m] - bm2[m]) * s;
  }
  int q = i - CF*CF - CO*CF - C2*C1 - CF;
  if (q >= 0 && q < C1){
    float s = bg1[q] * rsqrtf(bv1[q] + 1e-5f);
    g_w1f[q*4+0] = w1[q*3+0]*s;
    g_w1f[q*4+1] = w1[q*3+1]*s;
    g_w1f[q*4+2] = w1[q*3+2]*s;
    g_w1f[q*4+3] = (b1[q] - bm1[q])*s + bb1[q];
  }
}

// precompute h = relu(fold_bn1(xyz)) planes, sorted order. warp per point.
__global__ __launch_bounds__(256) void k_h(const float* __restrict__ xyz){
  const int t = threadIdx.x, lane = t & 31, wid = t >> 5;
  const int pt = blockIdx.x*8 + wid;
  const int pidx = g_perm[pt];
  const float x = xyz[(size_t)pidx*3+0];
  const float y = xyz[(size_t)pidx*3+1];
  const float z = xyz[(size_t)pidx*3+2];
  uint32_t oh[2], ol[2];
  #pragma unroll
  for (int p=0; p<2; p++){
    uint16_t hh[2], hl[2];
    #pragma unroll
    for (int j=0; j<2; j++){
      int k = lane*4 + p*2 + j;
      float4 wf = *(const float4*)(g_w1f + 4*k);
      float h = fmaf(x, wf.x, fmaf(y, wf.y, fmaf(z, wf.z, wf.w)));
      h = fmaxf(h, 0.f);
      split2(h, hh[j], hl[j]);
    }
    oh[p] = (uint32_t)hh[0] | ((uint32_t)hh[1] << 16);
    ol[p] = (uint32_t)hl[0] | ((uint32_t)hl[1] << 16);
  }
  *(uint2*)(g_h_h + (size_t)pt*C1 + lane*4) = make_uint2(oh[0], oh[1]);
  *(uint2*)(g_h_l + (size_t)pt*C1 + lane*4) = make_uint2(ol[0], ol[1]);
}

// =====================================================================
// Stage 1 (pure gemm now): feat = h @ w2^T + b2; segment-reduced fg max
// grid (2048, 2)
// =====================================================================
__global__ __launch_bounds__(256) void k_stage1(const float* __restrict__ b2)
{
  extern __shared__ char smem[];
  __shared__ int scl[128];

  const int t = threadIdx.x, lane = t & 31, wid = t >> 5;
  const int p0 = blockIdx.x*128, bb = blockIdx.x >> 6;
  const int ch0 = blockIdx.y*128;

  for (int i=t; i<128; i+=256) scl[i] = g_chs[p0+i];
  __syncthreads();

  Frag F;
  gemm_core(smem_u32(smem), p0, g_h_h, g_h_l, C1, ch0, g_w2_h, g_w2_l, C1, 0, C1/KC, F);

  float* Sv = (float*)smem;
  const int wm = (wid & 1)*64, wn = (wid >> 1)*32;
  const int r0 = lane >> 2, cp = (lane & 3)*2;
  #pragma unroll
  for (int mi=0;mi<4;mi++){
    int pa = wm + mi*16 + r0;
    size_t ga = (size_t)(p0 + pa), gb = ga + 8;
    #pragma unroll
    for (int ni=0;ni<4;ni++){
      int chl = wn + ni*8 + cp;
      int ch  = ch0 + chl;
      float b0 = b2[ch], b1v = b2[ch+1];
      float x0 = F.acc[mi][ni][0] + b0, x1 = F.acc[mi][ni][1] + b1v;
      float y0 = F.acc[mi][ni][2] + b0, y1 = F.acc[mi][ni][3] + b1v;
      uint16_t h0,l0,h1,l1;
      split2(x0,h0,l0); split2(x1,h1,l1);
      *(uint32_t*)(g_feat_h + ga*C2 + ch) = (uint32_t)h0 | ((uint32_t)h1<<16);
      *(uint32_t*)(g_feat_l + ga*C2 + ch) = (uint32_t)l0 | ((uint32_t)l1<<16);
      split2(y0,h0,l0); split2(y1,h1,l1);
      *(uint32_t*)(g_feat_h + gb*C2 + ch) = (uint32_t)h0 | ((uint32_t)h1<<16);
      *(uint32_t*)(g_feat_l + gb*C2 + ch) = (uint32_t)l0 | ((uint32_t)l1<<16);
      *(float2*)&Sv[(size_t)pa*SVSTR + chl]     = make_float2(x0, x1);
      *(float2*)&Sv[(size_t)(pa+8)*SVSTR + chl] = make_float2(y0, y1);
    }
  }
  __syncthreads();

  {
    const int ch = t & 127, half = t >> 7;
    int r = half*64;
    int cprev = scl[r];
    float run = __int_as_float(0xff800000);
    unsigned* fgb = &g_fg[(size_t)bb*NCLST*C2 + ch0 + ch];
    for (int i=0;i<64;i++,r++){
      int c = scl[r];
      if (c != cprev){
        atomicMax(&fgb[(size_t)cprev*C2], enc(run));
        run = __int_as_float(0xff800000);
        cprev = c;
      }
      run = fmaxf(run, Sv[(size_t)r*SVSTR + ch]);
    }
    atomicMax(&fgb[(size_t)cprev*C2], enc(run));
  }
}

__global__ void k_fg_split(){
  int i = blockIdx.x*blockDim.x + threadIdx.x;
  if (i < NFG*C2){
    uint16_t h,l; split2(dec(g_fg[i]), h, l);
    g_fg_h[i] = h; g_fg_l[i] = l;
  }
}

// =====================================================================
// Cluster GEMM: G = fg @ w3[:, :256]^T   grid (16, 4)
// =====================================================================
__global__ __launch_bounds__(256) void k_gemmC()
{
  extern __shared__ char smem[];
  const int t = threadIdx.x, lane = t & 31, wid = t >> 5;
  const int r0b = blockIdx.x*128;
  const int ch0 = blockIdx.y*128;

  Frag F;
  gemm_core(smem_u32(smem), r0b, g_fg_h, g_fg_l, C2, ch0, g_w3_h, g_w3_l, CF, 0, C2/KC, F);

  const int wm = (wid & 1)*64, wn = (wid >> 1)*32;
  const int r0 = lane >> 2, cp = (lane & 3)*2;
  #pragma unroll
  for (int mi=0;mi<4;mi++){
    size_t ga = (size_t)(r0b + wm + mi*16 + r0), gb = ga + 8;
    #pragma unroll
    for (int ni=0;ni<4;ni++){
      int ch = ch0 + wn + ni*8 + cp;
      *(float2*)(g_G + ga*CF + ch) = make_float2(F.acc[mi][ni][0], F.acc[mi][ni][1]);
      *(float2*)(g_G + gb*CF + ch) = make_float2(F.acc[mi][ni][2], F.acc[mi][ni][3]);
    }
  }
}

// =====================================================================
// GEMM2 (K=256): h2 = relu(bn2(feat @ w3[:,256:]^T + G[cluster]))
// grid (2048, 4)
// =====================================================================
__global__ __launch_bounds__(256) void k_gemm2()
{
  extern __shared__ char smem[];
  __shared__ int scl[128];
  const int t = threadIdx.x, lane = t & 31, wid = t >> 5;
  const int p0 = blockIdx.x*128, bb = blockIdx.x >> 6;
  const int ch0 = blockIdx.y*128;

  for (int i=t; i<128; i+=256) scl[i] = g_chs[p0+i];
  __syncthreads();

  Frag F;
  gemm_core(smem_u32(smem), p0, g_feat_h, g_feat_l, C2, ch0, g_w3_h, g_w3_l, CF, C2, C2/KC, F);

  const int wm = (wid & 1)*64, wn = (wid >> 1)*32;
  const int r0 = lane >> 2, cp = (lane & 3)*2;
  #pragma unroll
  for (int mi=0;mi<4;mi++){
    int pa = wm + mi*16 + r0;
    size_t ga = (size_t)(p0 + pa), gb = ga + 8;
    const float* Ga = &g_G[(size_t)(bb*NCLST + scl[pa])*CF];
    const float* Gb = &g_G[(size_t)(bb*NCLST + scl[pa+8])*CF];
    #pragma unroll
    for (int ni=0;ni<4;ni++){
      int ch = ch0 + wn + ni*8 + cp;
      float s0 = g_s2[ch], s1 = g_s2[ch+1];
      float t0 = g_t2[ch], t1 = g_t2[ch+1];
      float2 gva = *(const float2*)(Ga + ch);
      float2 gvb = *(const float2*)(Gb + ch);
      float x0 = fmaxf(fmaf(F.acc[mi][ni][0] + gva.x, s0, t0), 0.f);
      float x1 = fmaxf(fmaf(F.acc[mi][ni][1] + gva.y, s1, t1), 0.f);
      float y0 = fmaxf(fmaf(F.acc[mi][ni][2] + gvb.x, s0, t0), 0.f);
      float y1 = fmaxf(fmaf(F.acc[mi][ni][3] + gvb.y, s1, t1), 0.f);
      uint16_t h0,l0,h1,l1;
      split2(x0,h0,l0); split2(x1,h1,l1);
      *(uint32_t*)(g_h2_h + ga*CF + ch) = (uint32_t)h0 | ((uint32_t)h1<<16);
      *(uint32_t*)(g_h2_l + ga*CF + ch) = (uint32_t)l0 | ((uint32_t)l1<<16);
      split2(y0,h0,l0); split2(y1,h1,l1);
      *(uint32_t*)(g_h2_h + gb*CF + ch) = (uint32_t)h0 | ((uint32_t)h1<<16);
      *(uint32_t*)(g_h2_l + gb*CF + ch) = (uint32_t)l0 | ((uint32_t)l1<<16);
    }
  }
}

// =====================================================================
// GEMM3: out = h2 @ w4^T + b4 -> segment-reduced cluster max
// grid (2048, 3)
// =====================================================================
__global__ __launch_bounds__(256) void k_gemm3(const float* __restrict__ b4)
{
  extern __shared__ char smem[];
  __shared__ int scl[128];
  const int t = threadIdx.x, lane = t & 31, wid = t >> 5;
  const int p0 = blockIdx.x*128, bb = blockIdx.x >> 6;
  const int ch0 = blockIdx.y*128;

  for (int i=t; i<128; i+=256) scl[i] = g_chs[p0+i];
  __syncthreads();

  Frag F;
  gemm_core(smem_u32(smem), p0, g_h2_h, g_h2_l, CF, ch0, g_w4_h, g_w4_l, CF, 0, CF/KC, F);

  float* Sv = (float*)smem;
  const int wm = (wid & 1)*64, wn = (wid >> 1)*32;
  const int r0 = lane >> 2, cp = (lane & 3)*2;
  #pragma unroll
  for (int mi=0;mi<4;mi++){
    int pa = wm + mi*16 + r0;
    #pragma unroll
    for (int ni=0;ni<4;ni++){
      int chl = wn + ni*8 + cp;
      int ch  = ch0 + chl;
      float b0 = b4[ch], b1 = b4[ch+1];
      *(float2*)&Sv[(size_t)pa*SVSTR + chl] =
          make_float2(F.acc[mi][ni][0] + b0, F.acc[mi][ni][1] + b1);
      *(float2*)&Sv[(size_t)(pa+8)*SVSTR + chl] =
          make_float2(F.acc[mi][ni][2] + b0, F.acc[mi][ni][3] + b1);
    }
  }
  __syncthreads();

  {
    const int ch = t & 127, half = t >> 7;
    int r = half*64;
    int cprev = scl[r];
    float run = __int_as_float(0xff800000);
    unsigned* omb = &g_om[(size_t)bb*NCLST*CO + ch0 + ch];
    for (int i=0;i<64;i++,r++){
      int c = scl[r];
      if (c != cprev){
        atomicMax(&omb[(size_t)cprev*CO], enc(run));
        run = __int_as_float(0xff800000);
        cprev = c;
      }
      run = fmaxf(run, Sv[(size_t)r*SVSTR + ch]);
    }
    atomicMax(&omb[(size_t)cprev*CO], enc(run));
  }
}

__global__ void k_final(float* __restrict__ out){
  int i = blockIdx.x*blockDim.x + threadIdx.x;
  if (i < NFG*CO) out[i] = dec(g_om[i]);
}

// =====================================================================
extern "C" void kernel_launch(void* const* d_in, const int* in_sizes, int n_in,
                              void* d_out, int out_size)
{
  const float* xyz    = (const float*)d_in[0];
  const int*   choice = (const int*)  d_in[1];
  const float* w1  = (const float*)d_in[2];
  const float* b1  = (const float*)d_in[3];
  const float* g1  = (const float*)d_in[4];
  const float* bb1 = (const float*)d_in[5];
  const float* m1  = (const float*)d_in[6];
  const float* v1  = (const float*)d_in[7];
  const float* w2  = (const float*)d_in[8];
  const float* b2  = (const float*)d_in[9];
  const float* w3  = (const float*)d_in[10];
  const float* b3  = (const float*)d_in[11];
  const float* g2  = (const float*)d_in[12];
  const float* bb2 = (const float*)d_in[13];
  const float* m2  = (const float*)d_in[14];
  const float* v2  = (const float*)d_in[15];
  const float* w4  = (const float*)d_in[16];
  const float* b4  = (const float*)d_in[17];

  size_t smemg = 2*BUFB;      // 81920 (Sv 66560 fits inside)
  cudaFuncSetAttribute(k_stage1, cudaFuncAttributeMaxDynamicSharedMemorySize, (int)smemg);
  cudaFuncSetAttribute(k_gemmC,  cudaFuncAttributeMaxDynamicSharedMemorySize, (int)smemg);
  cudaFuncSetAttribute(k_gemm2,  cudaFuncAttributeMaxDynamicSharedMemorySize, (int)smemg);
  cudaFuncSetAttribute(k_gemm3,  cudaFuncAttributeMaxDynamicSharedMemorySize, (int)smemg);

  int ntot  = NFG*CO;
  int nprep = CF*CF + CO*CF + C2*C1 + CF + C1;

  k_init    <<<(ntot+255)/256, 256>>>();
  k_sort    <<<BATCH, 256>>>(choice);
  k_prep    <<<(nprep+255)/256, 256>>>(w1,b1,g1,bb1,m1,v1,w2, w3,w4,b3,g2,bb2,m2,v2);
  k_h       <<<PTOT/8, 256>>>(xyz);
  {
    dim3 g1d(PTOT/128, C2/128);   // (2048, 2)
    k_stage1<<<g1d, 256, smemg>>>(b2);
  }
  k_fg_split<<<(NFG*C2+255)/256, 256>>>();
  {
    dim3 gcd(NFG/128, CF/128);    // (16, 4)
    k_gemmC<<<gcd, 256, smemg>>>();
    dim3 g2d(PTOT/128, CF/128);   // (2048, 4)
    k_gemm2<<<g2d, 256, smemg>>>();
    dim3 g3d(PTOT/128, CO/128);   // (2048, 3)
    k_gemm3<<<g3d, 256, smemg>>>(b4);
  }
  k_final   <<<(ntot+255)/256, 256>>>((float*)d_out);
}